// round 1
// baseline (speedup 1.0000x reference)
#include <cuda_runtime.h>

// ---------------------------------------------------------------------------
// RWKV Tmix x060 block.  B=4, T=2048, C=2048, H=32, HS=64.
// Round 1: fully fp32 SIMT, correctness-first, structured for later tcgen05
// replacement of the two 68.7 GF GEMMs.
// ---------------------------------------------------------------------------

#define B_  4
#define T_  2048
#define C_  2048
#define H_  32
#define HS_ 64
#define MT_ (B_*T_)                       // 8192 rows
#define MTC_ ((size_t)MT_*(size_t)C_)     // 16777216 elements

// Scratch: 15 full-size [MT,C] buffers + xxx[8192,128] + h32[8192,32] + h128[8192,128]
__device__ __align__(128) float g_scratch[15ull*16777216ull + 4ull*1048576ull];

#define OFF_X    (0ull*16777216ull)
#define OFF_MIX0 (1ull*16777216ull)
#define OFF_MIX1 (2ull*16777216ull)
#define OFF_MIX2 (3ull*16777216ull)
#define OFF_MIX3 (4ull*16777216ull)
#define OFF_MW   (5ull*16777216ull)
#define OFF_XW   (6ull*16777216ull)
#define OFF_W    (7ull*16777216ull)
#define OFF_R    (8ull*16777216ull)
#define OFF_K    (9ull*16777216ull)
#define OFF_V    (10ull*16777216ull)
#define OFF_V2   (11ull*16777216ull)
#define OFF_DEC  (12ull*16777216ull)
#define OFF_Y    (13ull*16777216ull)
#define OFF_YN   (14ull*16777216ull)
#define OFF_XXX  (15ull*16777216ull)
#define OFF_H32  (OFF_XXX + 1048576ull)
#define OFF_H128 (OFF_H32 + 262144ull)

// ---------------------------------------------------------------------------
// Generic fp32 tiled GEMM.
//   C[m,n] = sum_k A[m,k] * B'[k,n]
//   BT=false: B is row-major [K,N] (ldb = row stride)
//   BT=true : B is row-major [N,K] (ldb = row stride)  -> C = A * B^T
// EPI: 0 = none, 1 = tanhf, 2 = += bias[n]
// All problem dims must divide the tile dims (true for every call below).
// ---------------------------------------------------------------------------
template<int BM,int BN,int BK,int TM,int TN,bool BT,int EPI>
__global__ void __launch_bounds__((BM/TM)*(BN/TN))
gemm_k(const float* __restrict__ A, const float* __restrict__ Bm,
       float* __restrict__ Cm, int M, int N, int K,
       int lda, int ldb, int ldc, const float* __restrict__ bias)
{
    constexpr int NT = (BM/TM)*(BN/TN);
    __shared__ float As[BK][BM+4];
    __shared__ float Bs[BK][BN+4];

    const int tid  = threadIdx.x;
    const int tx   = tid % (BN/TN);
    const int ty   = tid / (BN/TN);
    const int row0 = blockIdx.y * BM;
    const int col0 = blockIdx.x * BN;

    float acc[TM][TN];
#pragma unroll
    for (int i = 0; i < TM; i++)
#pragma unroll
        for (int j = 0; j < TN; j++) acc[i][j] = 0.f;

    for (int k0 = 0; k0 < K; k0 += BK) {
#pragma unroll
        for (int it = 0; it < (BM*BK)/NT; it++) {
            int i = tid + it*NT;
            int r = i / BK, c = i % BK;
            As[c][r] = A[(size_t)(row0 + r)*lda + (size_t)(k0 + c)];
        }
#pragma unroll
        for (int it = 0; it < (BK*BN)/NT; it++) {
            int i = tid + it*NT;
            if (BT) {
                int r = i / BK, c = i % BK;
                Bs[c][r] = Bm[(size_t)(col0 + r)*ldb + (size_t)(k0 + c)];
            } else {
                int r = i / BN, c = i % BN;
                Bs[r][c] = Bm[(size_t)(k0 + r)*ldb + (size_t)(col0 + c)];
            }
        }
        __syncthreads();
#pragma unroll
        for (int kk = 0; kk < BK; kk++) {
            float a[TM], b[TN];
#pragma unroll
            for (int i = 0; i < TM; i++) a[i] = As[kk][ty*TM + i];
#pragma unroll
            for (int j = 0; j < TN; j++) b[j] = Bs[kk][tx*TN + j];
#pragma unroll
            for (int i = 0; i < TM; i++)
#pragma unroll
                for (int j = 0; j < TN; j++)
                    acc[i][j] = fmaf(a[i], b[j], acc[i][j]);
        }
        __syncthreads();
    }

#pragma unroll
    for (int i = 0; i < TM; i++) {
        int rr = row0 + ty*TM + i;
#pragma unroll
        for (int j = 0; j < TN; j++) {
            int cc = col0 + tx*TN + j;
            float v = acc[i][j];
            if (EPI == 1) v = tanhf(v);
            if (EPI == 2) v += bias[cc];
            Cm[(size_t)rr*ldc + cc] = v;
        }
    }
}

// ---------------------------------------------------------------------------
// xw = x + dxprev * (time_maa_w + mw)
// ---------------------------------------------------------------------------
__global__ void xw_kernel(const float* __restrict__ x, const float* __restrict__ mw,
                          const float* __restrict__ shift, const float* __restrict__ maa_w,
                          float* __restrict__ xw)
{
    size_t idx = (size_t)blockIdx.x * blockDim.x + threadIdx.x;
    int   c  = (int)(idx & (C_-1));
    size_t bt = idx >> 11;
    int   t  = (int)(bt & (T_-1));
    int   b  = (int)(bt >> 11);
    float xv   = x[idx];
    float prev = t ? x[idx - C_] : shift[b*C_ + c];
    xw[idx] = xv + (prev - xv) * (maa_w[c] + mw[idx]);
}

// ---------------------------------------------------------------------------
// r, k, v, v2, decay from x, mixes, w.
// ---------------------------------------------------------------------------
__global__ void rkv_kernel(const float* __restrict__ x,  const float* __restrict__ shift,
                           const float* __restrict__ mr, const float* __restrict__ mk,
                           const float* __restrict__ mv, const float* __restrict__ mv2,
                           const float* __restrict__ w,
                           const float* __restrict__ maa_r, const float* __restrict__ maa_k,
                           const float* __restrict__ maa_v, const float* __restrict__ maa_v2,
                           const float* __restrict__ t_r,   const float* __restrict__ t_k,
                           float* __restrict__ r, float* __restrict__ k,
                           float* __restrict__ v, float* __restrict__ v2,
                           float* __restrict__ dec)
{
    size_t idx = (size_t)blockIdx.x * blockDim.x + threadIdx.x;
    int   c  = (int)(idx & (C_-1));
    size_t bt = idx >> 11;
    int   t  = (int)(bt & (T_-1));
    int   b  = (int)(bt >> 11);
    float xv   = x[idx];
    float prev = t ? x[idx - C_] : shift[b*C_ + c];
    float dx   = prev - xv;
    float d    = expf(-expf(w[idx]));
    r[idx]   = (xv + dx*(maa_r[c]  + mr[idx]))  * t_r[c];
    k[idx]   = (xv + dx*(maa_k[c]  + mk[idx]))  * t_k[c] * (1.f - d);
    v[idx]   =  xv + dx*(maa_v[c]  + mv[idx]);
    v2[idx]  =  xv + dx*(maa_v2[c] + mv2[idx]);
    dec[idx] = d;
}

// ---------------------------------------------------------------------------
// WKV6 scan (u = 0).  One block per (b,h).  256 threads: thread (q, j),
// q = tid&3 owns state rows [q*16, q*16+16) of column j = tid>>2, in regs.
// y_t = r_t @ S_{t-1};  S_t[i,j] = d_t[i]*S[i,j] + k_t[i]*v_t[j].
// Double-buffered smem staging, one barrier per step.
// ---------------------------------------------------------------------------
__global__ void __launch_bounds__(256) wkv_kernel(
    const float* __restrict__ r, const float* __restrict__ k,
    const float* __restrict__ v, const float* __restrict__ d,
    const float* __restrict__ s0, float* __restrict__ y)
{
    const int bh = blockIdx.x;
    const int b  = bh >> 5;        // H_ = 32
    const int h  = bh & 31;
    const int tid = threadIdx.x;
    const int q  = tid & 3;
    const int j  = tid >> 2;

    __shared__ float sbuf[2][4][64];   // [buf][r,k,v,d][64]

    float S[16];
    const size_t sbase = (size_t)bh * 64 * 64;
#pragma unroll
    for (int ii = 0; ii < 16; ii++)
        S[ii] = s0[sbase + (size_t)(q*16 + ii)*64 + j];

    const int arr = tid >> 6;          // which of the 4 arrays this thread stages
    const int li  = tid & 63;
    const float* src = (arr == 0) ? r : (arr == 1) ? k : (arr == 2) ? v : d;

    size_t base = (size_t)b * T_ * C_ + (size_t)h * 64;
    int p = 0;
    for (int t = 0; t < T_; t++) {
        sbuf[p][arr][li] = src[base + li];
        __syncthreads();

        const float  vv = sbuf[p][2][j];
        const float* rs = &sbuf[p][0][q*16];
        const float* ks = &sbuf[p][1][q*16];
        const float* ds = &sbuf[p][3][q*16];

        float y0 = 0.f, y1 = 0.f, y2 = 0.f, y3 = 0.f;
#pragma unroll
        for (int ii = 0; ii < 16; ii += 4) {
            float s0r = S[ii+0], s1r = S[ii+1], s2r = S[ii+2], s3r = S[ii+3];
            y0 = fmaf(rs[ii+0], s0r, y0);
            y1 = fmaf(rs[ii+1], s1r, y1);
            y2 = fmaf(rs[ii+2], s2r, y2);
            y3 = fmaf(rs[ii+3], s3r, y3);
            S[ii+0] = fmaf(ds[ii+0], s0r, ks[ii+0]*vv);
            S[ii+1] = fmaf(ds[ii+1], s1r, ks[ii+1]*vv);
            S[ii+2] = fmaf(ds[ii+2], s2r, ks[ii+2]*vv);
            S[ii+3] = fmaf(ds[ii+3], s3r, ks[ii+3]*vv);
        }
        float yp = (y0 + y1) + (y2 + y3);
        yp += __shfl_xor_sync(0xffffffffu, yp, 1);
        yp += __shfl_xor_sync(0xffffffffu, yp, 2);
        if (q == 0) y[base + j] = yp;

        base += C_;
        p ^= 1;
    }
}

// ---------------------------------------------------------------------------
// y = LayerNorm(y + v2) * gamma + beta.  One block per row.
// ---------------------------------------------------------------------------
__global__ void __launch_bounds__(256) ln_kernel(
    const float* __restrict__ y, const float* __restrict__ v2,
    const float* __restrict__ gamma, const float* __restrict__ beta,
    float* __restrict__ out)
{
    const int row = blockIdx.x;
    const int tid = threadIdx.x;
    __shared__ float buf[C_];
    __shared__ float aux[2][8];

    const size_t base = (size_t)row * C_;
    float s = 0.f, s2 = 0.f;
    for (int c = tid; c < C_; c += 256) {
        float val = y[base + c] + v2[base + c];
        buf[c] = val;
        s += val; s2 += val*val;
    }
#pragma unroll
    for (int o = 16; o; o >>= 1) {
        s  += __shfl_xor_sync(0xffffffffu, s,  o);
        s2 += __shfl_xor_sync(0xffffffffu, s2, o);
    }
    if ((tid & 31) == 0) { aux[0][tid >> 5] = s; aux[1][tid >> 5] = s2; }
    __syncthreads();
    float ts = 0.f, ts2 = 0.f;
#pragma unroll
    for (int wpi = 0; wpi < 8; wpi++) { ts += aux[0][wpi]; ts2 += aux[1][wpi]; }
    const float mu  = ts * (1.f / C_);
    const float var = ts2 * (1.f / C_) - mu*mu;
    const float inv = rsqrtf(var + 1e-5f);
    for (int c = tid; c < C_; c += 256)
        out[base + c] = (buf[c] - mu) * inv * gamma[c] + beta[c];
}

// ---------------------------------------------------------------------------
extern "C" void kernel_launch(void* const* d_in, const int* in_sizes, int n_in,
                              void* d_out, int out_size)
{
    const float* x_in    = (const float*)d_in[0];
    const float* shift   = (const float*)d_in[1];
    const float* wkv_s   = (const float*)d_in[2];
    const float* maa_r   = (const float*)d_in[3];
    const float* maa_k   = (const float*)d_in[4];
    const float* maa_v   = (const float*)d_in[5];
    const float* maa_v2  = (const float*)d_in[6];
    const float* maa_w1  = (const float*)d_in[7];
    const float* maa_w2  = (const float*)d_in[8];
    const float* maa_w   = (const float*)d_in[9];
    const float* w_w1    = (const float*)d_in[10];
    const float* w_w2    = (const float*)d_in[11];
    const float* t_decay = (const float*)d_in[12];
    const float* dec_w1  = (const float*)d_in[13];
    const float* dec_w2  = (const float*)d_in[14];
    /* d_in[15] time_faaaa: dead (u = 0 in reference) */
    const float* t_rec   = (const float*)d_in[16];
    const float* t_key   = (const float*)d_in[17];
    const float* val_w   = (const float*)d_in[18];
    const float* out_w   = (const float*)d_in[19];
    const float* gamma   = (const float*)d_in[20];
    const float* beta    = (const float*)d_in[21];
    float* outp = (float*)d_out;

    float* sp = nullptr;
    cudaGetSymbolAddress((void**)&sp, g_scratch);
    float* gx    = sp + OFF_X;
    float* gmix0 = sp + OFF_MIX0;
    float* gmix1 = sp + OFF_MIX1;
    float* gmix2 = sp + OFF_MIX2;
    float* gmix3 = sp + OFF_MIX3;
    float* gmw   = sp + OFF_MW;
    float* gxw   = sp + OFF_XW;
    float* gw    = sp + OFF_W;
    float* gr    = sp + OFF_R;
    float* gk    = sp + OFF_K;
    float* gv    = sp + OFF_V;
    float* gv2   = sp + OFF_V2;
    float* gdec  = sp + OFF_DEC;
    float* gy    = sp + OFF_Y;
    float* gyn   = sp + OFF_YN;
    float* gxxx  = sp + OFF_XXX;
    float* gh32  = sp + OFF_H32;
    float* gh128 = sp + OFF_H128;
    float* gmixf[4] = {gmix0, gmix1, gmix2, gmix3};

    const dim3 gBig(C_/128, MT_/128);          // (16, 64)
    const unsigned ewBlocks = (unsigned)(MTC_ / 256);

    // 1) x = x_in @ value_w^T
    gemm_k<128,128,16,8,8,true,0><<<gBig,256>>>(x_in, val_w, gx,
        MT_, C_, C_, C_, C_, C_, nullptr);

    // 2) xxx = tanh(x_in @ time_maa_w1)        [8192,128]
    gemm_k<64,32,32,4,4,false,1><<<dim3(128/32, MT_/64),128>>>(x_in, maa_w1, gxxx,
        MT_, 128, C_, C_, 128, 128, nullptr);

    // 3) mix_f = xxx[:, f*32:(f+1)*32] @ time_maa_w2[f]   (K=32 expansions)
    for (int f = 0; f < 4; f++)
        gemm_k<128,128,16,8,8,false,0><<<gBig,256>>>(gxxx + f*32,
            maa_w2 + (size_t)f*32*C_, gmixf[f],
            MT_, C_, 32, 128, C_, C_, nullptr);

    // 4) h32 = tanh(x @ time_maa_w_w1)         [8192,32]
    gemm_k<64,32,32,4,4,false,1><<<dim3(1, MT_/64),128>>>(gx, w_w1, gh32,
        MT_, 32, C_, C_, 32, 32, nullptr);

    // 5) mw = h32 @ time_maa_w_w2
    gemm_k<128,128,16,8,8,false,0><<<gBig,256>>>(gh32, w_w2, gmw,
        MT_, C_, 32, 32, C_, C_, nullptr);

    // 6) xw = x + dxprev*(time_maa_w + mw)
    xw_kernel<<<ewBlocks,256>>>(gx, gmw, shift, maa_w, gxw);

    // 7) h128 = tanh(xw @ time_decay_w1)       [8192,128]
    gemm_k<64,32,32,4,4,false,1><<<dim3(128/32, MT_/64),128>>>(gxw, dec_w1, gh128,
        MT_, 128, C_, C_, 128, 128, nullptr);

    // 8) w = time_decay + h128 @ time_decay_w2
    gemm_k<128,128,16,8,8,false,2><<<gBig,256>>>(gh128, dec_w2, gw,
        MT_, C_, 128, 128, C_, C_, t_decay);

    // 9) r,k,v,v2,decay
    rkv_kernel<<<ewBlocks,256>>>(gx, shift, gmix0, gmix1, gmix2, gmix3, gw,
        maa_r, maa_k, maa_v, maa_v2, t_rec, t_key,
        gr, gk, gv, gv2, gdec);

    // 10) WKV6 scan
    wkv_kernel<<<B_*H_,256>>>(gr, gk, gv, gdec, wkv_s, gy);

    // 11) LayerNorm(y + v2)
    ln_kernel<<<MT_,256>>>(gy, gv2, gamma, beta, gyn);

    // 12) out = ynorm @ output_w^T
    gemm_k<128,128,16,8,8,true,0><<<gBig,256>>>(gyn, out_w, outp,
        MT_, C_, C_, C_, C_, C_, nullptr);

    (void)in_sizes; (void)n_in; (void)out_size;
}

// round 4
// speedup vs baseline: 1.5173x; 1.5173x over previous
#include <cuda_runtime.h>
#include <cuda_bf16.h>
#include <cstdint>

// ---------------------------------------------------------------------------
// RWKV Tmix x060 block.  B=4, T=2048, C=2048, H=32, HS=64.
// Round 4: tcgen05 is unusable (harness compiles via compute_103 PTX, which
// rejects tcgen05).  The two 68.7 GF C x C GEMMs now use mma.sync bf16
// (split hi/lo, 3-term) with cp.async double buffering.  Rest unchanged.
// ---------------------------------------------------------------------------

#define B_  4
#define T_  2048
#define C_  2048
#define H_  32
#define HS_ 64
#define MT_ (B_*T_)                       // 8192 rows
#define MTC_ ((size_t)MT_*(size_t)C_)     // 16777216 elements

__device__ __align__(128) float g_scratch[15ull*16777216ull + 4ull*1048576ull];

#define OFF_X    (0ull*16777216ull)
#define OFF_MIX0 (1ull*16777216ull)
#define OFF_MIX1 (2ull*16777216ull)
#define OFF_MIX2 (3ull*16777216ull)
#define OFF_MIX3 (4ull*16777216ull)
#define OFF_MW   (5ull*16777216ull)
#define OFF_XW   (6ull*16777216ull)
#define OFF_W    (7ull*16777216ull)
#define OFF_R    (8ull*16777216ull)
#define OFF_K    (9ull*16777216ull)
#define OFF_V    (10ull*16777216ull)
#define OFF_V2   (11ull*16777216ull)
#define OFF_DEC  (12ull*16777216ull)
#define OFF_Y    (13ull*16777216ull)
#define OFF_XXX  (15ull*16777216ull)
#define OFF_H32  (OFF_XXX + 1048576ull)
#define OFF_H128 (OFF_H32 + 262144ull)

// bf16 hi/lo buffers: x_in (hi,lo), yn (hi,lo), value_w (hi,lo), output_w (hi,lo)
__device__ __align__(128) __nv_bfloat16 g_bf16[4ull*16777216ull + 4ull*4194304ull];
#define BF_XH  (0ull*16777216ull)
#define BF_XL  (1ull*16777216ull)
#define BF_YH  (2ull*16777216ull)
#define BF_YL  (3ull*16777216ull)
#define BF_VWH (4ull*16777216ull)
#define BF_VWL (BF_VWH + 4194304ull)
#define BF_OWH (BF_VWL + 4194304ull)
#define BF_OWL (BF_OWH + 4194304ull)

// ======================== mma.sync helpers =================================
__device__ __forceinline__ uint32_t smem_u32(const void* p) {
    uint32_t a;
    asm("{ .reg .u64 t; cvta.to.shared.u64 t, %1; cvt.u32.u64 %0, t; }" : "=r"(a) : "l"(p));
    return a;
}

__device__ __forceinline__ void mma16816(float* d, const uint32_t* a, const uint32_t* b) {
    asm volatile(
        "mma.sync.aligned.m16n8k16.row.col.f32.bf16.bf16.f32 "
        "{%0,%1,%2,%3}, {%4,%5,%6,%7}, {%8,%9}, {%0,%1,%2,%3};"
        : "+f"(d[0]), "+f"(d[1]), "+f"(d[2]), "+f"(d[3])
        : "r"(a[0]), "r"(a[1]), "r"(a[2]), "r"(a[3]), "r"(b[0]), "r"(b[1]));
}

__device__ __forceinline__ void ldsm4(uint32_t* r, uint32_t addr) {
    asm volatile("ldmatrix.sync.aligned.m8n8.x4.shared.b16 {%0,%1,%2,%3}, [%4];"
        : "=r"(r[0]), "=r"(r[1]), "=r"(r[2]), "=r"(r[3]) : "r"(addr));
}

__device__ __forceinline__ void cp16(uint32_t dst, const void* src) {
    asm volatile("cp.async.cg.shared.global [%0], [%1], 16;" :: "r"(dst), "l"(src));
}
#define CP_COMMIT() asm volatile("cp.async.commit_group;" ::: "memory")
#define CP_WAIT(n)  asm volatile("cp.async.wait_group %0;" :: "n"(n) : "memory")

// ---------------------------------------------------------------------------
// Split-bf16 mma.sync GEMM:  C[8192,2048] = A @ B^T
// A,B as (hi,lo) bf16 row-major [rows, 2048] (K contiguous on both sides).
// Block tile 128x128, BK=32, 8 warps (warp tile 64x32), cp.async 2-stage.
// smem tile pitch = 40 bf16 (80B) -> conflict-free ldmatrix.
// ---------------------------------------------------------------------------
#define GM_PITCH   40            // bf16 elements per smem row
#define GM_TILE_B  10240u        // 128 * 80 bytes
#define GM_BUF_B   40960u        // 4 tiles
#define GM_SMEM    81920         // 2 buffers

__global__ void __launch_bounds__(256, 2) gemm_mma(
    const __nv_bfloat16* __restrict__ a_hi, const __nv_bfloat16* __restrict__ a_lo,
    const __nv_bfloat16* __restrict__ b_hi, const __nv_bfloat16* __restrict__ b_lo,
    float* __restrict__ Cm)
{
    extern __shared__ char smem[];
    const uint32_t sbase = smem_u32(smem);

    const int tid    = threadIdx.x;
    const int lane   = tid & 31;
    const int wid    = tid >> 5;
    const int warp_m = wid & 1;          // 2 warps over M
    const int warp_n = wid >> 1;         // 4 warps over N
    const int row0   = blockIdx.y * 128;
    const int col0   = blockIdx.x * 128;

    const __nv_bfloat16* sA0 = a_hi + (size_t)row0 * 2048;
    const __nv_bfloat16* sA1 = a_lo + (size_t)row0 * 2048;
    const __nv_bfloat16* sB0 = b_hi + (size_t)col0 * 2048;
    const __nv_bfloat16* sB1 = b_lo + (size_t)col0 * 2048;

    // per-thread static load coords: 512 x 16B per tile, 2 per thread per tile
    const int rr0 = tid >> 2;            // rows 0..63   (s=0)
    const int rr1 = rr0 + 64;            // rows 64..127 (s=1)
    const int cc  = (tid & 3) * 8;       // bf16 offset within 32-elem row chunk

    auto issue = [&](int ch, int buf) {
        const uint32_t bb = sbase + (uint32_t)buf * GM_BUF_B;
        const int kel = ch * 32;
#define ONE_TILE(SRC, TOFF)                                                    \
        cp16(bb + (TOFF) + (uint32_t)rr0*80u + (uint32_t)(tid&3)*16u,          \
             (SRC) + (size_t)rr0*2048 + kel + cc);                             \
        cp16(bb + (TOFF) + (uint32_t)rr1*80u + (uint32_t)(tid&3)*16u,          \
             (SRC) + (size_t)rr1*2048 + kel + cc);
        ONE_TILE(sA0, 0u)
        ONE_TILE(sA1, GM_TILE_B)
        ONE_TILE(sB0, 2u*GM_TILE_B)
        ONE_TILE(sB1, 3u*GM_TILE_B)
#undef ONE_TILE
        CP_COMMIT();
    };

    float acc[4][4][4];
#pragma unroll
    for (int i = 0; i < 4; i++)
#pragma unroll
        for (int j = 0; j < 4; j++)
#pragma unroll
            for (int q = 0; q < 4; q++) acc[i][j][q] = 0.f;

    issue(0, 0);

    // ldmatrix lane addressing pieces (row = lane%16, k-half = lane/16)
    const uint32_t lrow = (uint32_t)(lane & 15);
    const uint32_t khalf = (uint32_t)((lane >> 4) << 3);   // 0 or 8 (bf16 elems)

    for (int ch = 0; ch < 64; ch++) {
        if (ch < 63) { issue(ch + 1, (ch + 1) & 1); CP_WAIT(1); }
        else         { CP_WAIT(0); }
        __syncthreads();

        const uint32_t bb  = sbase + (uint32_t)(ch & 1) * GM_BUF_B;
        const uint32_t aH  = bb;
        const uint32_t aL  = bb + GM_TILE_B;
        const uint32_t bH  = bb + 2u*GM_TILE_B;
        const uint32_t bL  = bb + 3u*GM_TILE_B;

#pragma unroll
        for (int k16 = 0; k16 < 32; k16 += 16) {
            const uint32_t kb = ((uint32_t)k16 + khalf) * 2u;   // byte offset in row
            uint32_t af[4][4], bf[4][2], bl[4][2];

            // A hi: 4 m16 frags (rows warp_m*64 + f*16 + lrow)
#pragma unroll
            for (int f = 0; f < 4; f++)
                ldsm4(af[f], aH + (uint32_t)(warp_m*64 + f*16 + lrow)*80u + kb);
            // B hi: 2 x4 -> 4 n8 frags
#pragma unroll
            for (int pr = 0; pr < 2; pr++) {
                uint32_t r[4];
                ldsm4(r, bH + (uint32_t)(warp_n*32 + pr*16 + lrow)*80u + kb);
                bf[2*pr+0][0] = r[0]; bf[2*pr+0][1] = r[2];
                bf[2*pr+1][0] = r[1]; bf[2*pr+1][1] = r[3];
            }
            // B lo
#pragma unroll
            for (int pr = 0; pr < 2; pr++) {
                uint32_t r[4];
                ldsm4(r, bL + (uint32_t)(warp_n*32 + pr*16 + lrow)*80u + kb);
                bl[2*pr+0][0] = r[0]; bl[2*pr+0][1] = r[2];
                bl[2*pr+1][0] = r[1]; bl[2*pr+1][1] = r[3];
            }
            // hh + hl
#pragma unroll
            for (int mf = 0; mf < 4; mf++)
#pragma unroll
                for (int nf = 0; nf < 4; nf++) {
                    mma16816(acc[mf][nf], af[mf], bf[nf]);
                    mma16816(acc[mf][nf], af[mf], bl[nf]);
                }
            // A lo over A hi, then lh with B hi
#pragma unroll
            for (int f = 0; f < 4; f++)
                ldsm4(af[f], aL + (uint32_t)(warp_m*64 + f*16 + lrow)*80u + kb);
#pragma unroll
            for (int mf = 0; mf < 4; mf++)
#pragma unroll
                for (int nf = 0; nf < 4; nf++)
                    mma16816(acc[mf][nf], af[mf], bf[nf]);
        }
        __syncthreads();
    }

    // epilogue: c-frag layout m16n8: t -> (row = t/4 (+8), col = 2*(t%4))
    const int erow = row0 + warp_m*64 + (lane >> 2);
    const int ecol = col0 + warp_n*32 + (lane & 3)*2;
#pragma unroll
    for (int mf = 0; mf < 4; mf++) {
#pragma unroll
        for (int nf = 0; nf < 4; nf++) {
            float* p0 = Cm + (size_t)(erow + mf*16    )*2048 + ecol + nf*8;
            float* p1 = Cm + (size_t)(erow + mf*16 + 8)*2048 + ecol + nf*8;
            *(float2*)p0 = make_float2(acc[mf][nf][0], acc[mf][nf][1]);
            *(float2*)p1 = make_float2(acc[mf][nf][2], acc[mf][nf][3]);
        }
    }
}

// ---------------------------------------------------------------------------
// fp32 -> (hi, lo) bf16 conversion, vectorized by 4.
// ---------------------------------------------------------------------------
__global__ void cvt_hilo(const float* __restrict__ in,
                         __nv_bfloat16* __restrict__ hi,
                         __nv_bfloat16* __restrict__ lo, int n4)
{
    int i = blockIdx.x * blockDim.x + threadIdx.x;
    if (i >= n4) return;
    float4 f = ((const float4*)in)[i];
    __nv_bfloat16 h0 = __float2bfloat16(f.x), h1 = __float2bfloat16(f.y);
    __nv_bfloat16 h2 = __float2bfloat16(f.z), h3 = __float2bfloat16(f.w);
    __nv_bfloat16 l0 = __float2bfloat16(f.x - __bfloat162float(h0));
    __nv_bfloat16 l1 = __float2bfloat16(f.y - __bfloat162float(h1));
    __nv_bfloat16 l2 = __float2bfloat16(f.z - __bfloat162float(h2));
    __nv_bfloat16 l3 = __float2bfloat16(f.w - __bfloat162float(h3));
    uint2 up, lp;
    ((__nv_bfloat16*)&up)[0] = h0; ((__nv_bfloat16*)&up)[1] = h1;
    ((__nv_bfloat16*)&up)[2] = h2; ((__nv_bfloat16*)&up)[3] = h3;
    ((__nv_bfloat16*)&lp)[0] = l0; ((__nv_bfloat16*)&lp)[1] = l1;
    ((__nv_bfloat16*)&lp)[2] = l2; ((__nv_bfloat16*)&lp)[3] = l3;
    ((uint2*)hi)[i] = up;
    ((uint2*)lo)[i] = lp;
}

// ======================== fp32 SIMT GEMM (small GEMMs) =====================
template<int BM,int BN,int BK,int TM,int TN,bool BT,int EPI>
__global__ void __launch_bounds__((BM/TM)*(BN/TN))
gemm_k(const float* __restrict__ A, const float* __restrict__ Bm,
       float* __restrict__ Cm, int M, int N, int K,
       int lda, int ldb, int ldc, const float* __restrict__ bias)
{
    constexpr int NT = (BM/TM)*(BN/TN);
    __shared__ float As[BK][BM+4];
    __shared__ float Bs[BK][BN+4];

    const int tid  = threadIdx.x;
    const int tx   = tid % (BN/TN);
    const int ty   = tid / (BN/TN);
    const int row0 = blockIdx.y * BM;
    const int col0 = blockIdx.x * BN;

    float acc[TM][TN];
#pragma unroll
    for (int i = 0; i < TM; i++)
#pragma unroll
        for (int j = 0; j < TN; j++) acc[i][j] = 0.f;

    for (int k0 = 0; k0 < K; k0 += BK) {
#pragma unroll
        for (int it = 0; it < (BM*BK)/NT; it++) {
            int i = tid + it*NT;
            int r = i / BK, c = i % BK;
            As[c][r] = A[(size_t)(row0 + r)*lda + (size_t)(k0 + c)];
        }
#pragma unroll
        for (int it = 0; it < (BK*BN)/NT; it++) {
            int i = tid + it*NT;
            if (BT) {
                int r = i / BK, c = i % BK;
                Bs[c][r] = Bm[(size_t)(col0 + r)*ldb + (size_t)(k0 + c)];
            } else {
                int r = i / BN, c = i % BN;
                Bs[r][c] = Bm[(size_t)(k0 + r)*ldb + (size_t)(col0 + c)];
            }
        }
        __syncthreads();
#pragma unroll
        for (int kk = 0; kk < BK; kk++) {
            float a[TM], b[TN];
#pragma unroll
            for (int i = 0; i < TM; i++) a[i] = As[kk][ty*TM + i];
#pragma unroll
            for (int j = 0; j < TN; j++) b[j] = Bs[kk][tx*TN + j];
#pragma unroll
            for (int i = 0; i < TM; i++)
#pragma unroll
                for (int j = 0; j < TN; j++)
                    acc[i][j] = fmaf(a[i], b[j], acc[i][j]);
        }
        __syncthreads();
    }

#pragma unroll
    for (int i = 0; i < TM; i++) {
        int rr = row0 + ty*TM + i;
#pragma unroll
        for (int j = 0; j < TN; j++) {
            int cc = col0 + tx*TN + j;
            float v = acc[i][j];
            if (EPI == 1) v = tanhf(v);
            if (EPI == 2) v += bias[cc];
            Cm[(size_t)rr*ldc + cc] = v;
        }
    }
}

// ======================== elementwise / scan / LN ==========================
__global__ void xw_kernel(const float* __restrict__ x, const float* __restrict__ mw,
                          const float* __restrict__ shift, const float* __restrict__ maa_w,
                          float* __restrict__ xw)
{
    size_t idx = (size_t)blockIdx.x * blockDim.x + threadIdx.x;
    int   c  = (int)(idx & (C_-1));
    size_t bt = idx >> 11;
    int   t  = (int)(bt & (T_-1));
    int   b  = (int)(bt >> 11);
    float xv   = x[idx];
    float prev = t ? x[idx - C_] : shift[b*C_ + c];
    xw[idx] = xv + (prev - xv) * (maa_w[c] + mw[idx]);
}

__global__ void rkv_kernel(const float* __restrict__ x,  const float* __restrict__ shift,
                           const float* __restrict__ mr, const float* __restrict__ mk,
                           const float* __restrict__ mv, const float* __restrict__ mv2,
                           const float* __restrict__ w,
                           const float* __restrict__ maa_r, const float* __restrict__ maa_k,
                           const float* __restrict__ maa_v, const float* __restrict__ maa_v2,
                           const float* __restrict__ t_r,   const float* __restrict__ t_k,
                           float* __restrict__ r, float* __restrict__ k,
                           float* __restrict__ v, float* __restrict__ v2,
                           float* __restrict__ dec)
{
    size_t idx = (size_t)blockIdx.x * blockDim.x + threadIdx.x;
    int   c  = (int)(idx & (C_-1));
    size_t bt = idx >> 11;
    int   t  = (int)(bt & (T_-1));
    int   b  = (int)(bt >> 11);
    float xv   = x[idx];
    float prev = t ? x[idx - C_] : shift[b*C_ + c];
    float dx   = prev - xv;
    float d    = expf(-expf(w[idx]));
    r[idx]   = (xv + dx*(maa_r[c]  + mr[idx]))  * t_r[c];
    k[idx]   = (xv + dx*(maa_k[c]  + mk[idx]))  * t_k[c] * (1.f - d);
    v[idx]   =  xv + dx*(maa_v[c]  + mv[idx]);
    v2[idx]  =  xv + dx*(maa_v2[c] + mv2[idx]);
    dec[idx] = d;
}

__global__ void __launch_bounds__(256) wkv_kernel(
    const float* __restrict__ r, const float* __restrict__ k,
    const float* __restrict__ v, const float* __restrict__ d,
    const float* __restrict__ s0, float* __restrict__ y)
{
    const int bh = blockIdx.x;
    const int b  = bh >> 5;
    const int h  = bh & 31;
    const int tid = threadIdx.x;
    const int q  = tid & 3;
    const int j  = tid >> 2;

    __shared__ float sbuf[2][4][64];

    float S[16];
    const size_t sbase = (size_t)bh * 64 * 64;
#pragma unroll
    for (int ii = 0; ii < 16; ii++)
        S[ii] = s0[sbase + (size_t)(q*16 + ii)*64 + j];

    const int arr = tid >> 6;
    const int li  = tid & 63;
    const float* src = (arr == 0) ? r : (arr == 1) ? k : (arr == 2) ? v : d;

    size_t base = (size_t)b * T_ * C_ + (size_t)h * 64;
    int p = 0;
    for (int t = 0; t < T_; t++) {
        sbuf[p][arr][li] = src[base + li];
        __syncthreads();

        const float  vv = sbuf[p][2][j];
        const float* rs = &sbuf[p][0][q*16];
        const float* ks = &sbuf[p][1][q*16];
        const float* ds = &sbuf[p][3][q*16];

        float y0 = 0.f, y1 = 0.f, y2 = 0.f, y3 = 0.f;
#pragma unroll
        for (int ii = 0; ii < 16; ii += 4) {
            float s0r = S[ii+0], s1r = S[ii+1], s2r = S[ii+2], s3r = S[ii+3];
            y0 = fmaf(rs[ii+0], s0r, y0);
            y1 = fmaf(rs[ii+1], s1r, y1);
            y2 = fmaf(rs[ii+2], s2r, y2);
            y3 = fmaf(rs[ii+3], s3r, y3);
            S[ii+0] = fmaf(ds[ii+0], s0r, ks[ii+0]*vv);
            S[ii+1] = fmaf(ds[ii+1], s1r, ks[ii+1]*vv);
            S[ii+2] = fmaf(ds[ii+2], s2r, ks[ii+2]*vv);
            S[ii+3] = fmaf(ds[ii+3], s3r, ks[ii+3]*vv);
        }
        float yp = (y0 + y1) + (y2 + y3);
        yp += __shfl_xor_sync(0xffffffffu, yp, 1);
        yp += __shfl_xor_sync(0xffffffffu, yp, 2);
        if (q == 0) y[base + j] = yp;

        base += C_;
        p ^= 1;
    }
}

// LayerNorm(y + v2); writes hi/lo bf16 directly (feeds the mma GEMM).
__global__ void __launch_bounds__(256) ln_kernel(
    const float* __restrict__ y, const float* __restrict__ v2,
    const float* __restrict__ gamma, const float* __restrict__ beta,
    __nv_bfloat16* __restrict__ yh, __nv_bfloat16* __restrict__ yl)
{
    const int row = blockIdx.x;
    const int tid = threadIdx.x;
    __shared__ float buf[C_];
    __shared__ float aux[2][8];

    const size_t base = (size_t)row * C_;
    float s = 0.f, s2 = 0.f;
    for (int c = tid; c < C_; c += 256) {
        float val = y[base + c] + v2[base + c];
        buf[c] = val;
        s += val; s2 += val*val;
    }
#pragma unroll
    for (int o = 16; o; o >>= 1) {
        s  += __shfl_xor_sync(0xffffffffu, s,  o);
        s2 += __shfl_xor_sync(0xffffffffu, s2, o);
    }
    if ((tid & 31) == 0) { aux[0][tid >> 5] = s; aux[1][tid >> 5] = s2; }
    __syncthreads();
    float ts = 0.f, ts2 = 0.f;
#pragma unroll
    for (int wpi = 0; wpi < 8; wpi++) { ts += aux[0][wpi]; ts2 += aux[1][wpi]; }
    const float mu  = ts * (1.f / C_);
    const float var = ts2 * (1.f / C_) - mu*mu;
    const float inv = rsqrtf(var + 1e-5f);
    for (int c = tid; c < C_; c += 256) {
        float o = (buf[c] - mu) * inv * gamma[c] + beta[c];
        __nv_bfloat16 h = __float2bfloat16(o);
        yh[base + c] = h;
        yl[base + c] = __float2bfloat16(o - __bfloat162float(h));
    }
}

// ---------------------------------------------------------------------------
extern "C" void kernel_launch(void* const* d_in, const int* in_sizes, int n_in,
                              void* d_out, int out_size)
{
    const float* x_in    = (const float*)d_in[0];
    const float* shift   = (const float*)d_in[1];
    const float* wkv_s   = (const float*)d_in[2];
    const float* maa_r   = (const float*)d_in[3];
    const float* maa_k   = (const float*)d_in[4];
    const float* maa_v   = (const float*)d_in[5];
    const float* maa_v2  = (const float*)d_in[6];
    const float* maa_w1  = (const float*)d_in[7];
    const float* maa_w2  = (const float*)d_in[8];
    const float* maa_w   = (const float*)d_in[9];
    const float* w_w1    = (const float*)d_in[10];
    const float* w_w2    = (const float*)d_in[11];
    const float* t_decay = (const float*)d_in[12];
    const float* dec_w1  = (const float*)d_in[13];
    const float* dec_w2  = (const float*)d_in[14];
    /* d_in[15] time_faaaa: dead (u = 0 in reference) */
    const float* t_rec   = (const float*)d_in[16];
    const float* t_key   = (const float*)d_in[17];
    const float* val_w   = (const float*)d_in[18];
    const float* out_w   = (const float*)d_in[19];
    const float* gamma   = (const float*)d_in[20];
    const float* beta    = (const float*)d_in[21];
    float* outp = (float*)d_out;

    float* sp = nullptr;
    cudaGetSymbolAddress((void**)&sp, g_scratch);
    __nv_bfloat16* bp = nullptr;
    cudaGetSymbolAddress((void**)&bp, g_bf16);

    float* gx    = sp + OFF_X;
    float* gmix0 = sp + OFF_MIX0;
    float* gmix1 = sp + OFF_MIX1;
    float* gmix2 = sp + OFF_MIX2;
    float* gmix3 = sp + OFF_MIX3;
    float* gmw   = sp + OFF_MW;
    float* gxw   = sp + OFF_XW;
    float* gw    = sp + OFF_W;
    float* gr    = sp + OFF_R;
    float* gk    = sp + OFF_K;
    float* gv    = sp + OFF_V;
    float* gv2   = sp + OFF_V2;
    float* gdec  = sp + OFF_DEC;
    float* gy    = sp + OFF_Y;
    float* gxxx  = sp + OFF_XXX;
    float* gh32  = sp + OFF_H32;
    float* gh128 = sp + OFF_H128;
    float* gmixf[4] = {gmix0, gmix1, gmix2, gmix3};

    __nv_bfloat16* xh  = bp + BF_XH;
    __nv_bfloat16* xl  = bp + BF_XL;
    __nv_bfloat16* yh  = bp + BF_YH;
    __nv_bfloat16* yl  = bp + BF_YL;
    __nv_bfloat16* vwh = bp + BF_VWH;
    __nv_bfloat16* vwl = bp + BF_VWL;
    __nv_bfloat16* owh = bp + BF_OWH;
    __nv_bfloat16* owl = bp + BF_OWL;

    cudaFuncSetAttribute(gemm_mma, cudaFuncAttributeMaxDynamicSharedMemorySize, GM_SMEM);

    const dim3 gBig(C_/128, MT_/128);          // (16, 64)
    const unsigned ewBlocks = (unsigned)(MTC_ / 256);

    // 0) conversions for the tensor-core GEMMs
    cvt_hilo<<<(unsigned)(MTC_/4/256), 256>>>(x_in,  xh,  xl,  (int)(MTC_/4));
    cvt_hilo<<<(unsigned)(C_*(size_t)C_/4/256), 256>>>(val_w, vwh, vwl, C_*C_/4);
    cvt_hilo<<<(unsigned)(C_*(size_t)C_/4/256), 256>>>(out_w, owh, owl, C_*C_/4);

    // 1) x = x_in @ value_w^T     (mma.sync, split-bf16)
    gemm_mma<<<gBig, 256, GM_SMEM>>>(xh, xl, vwh, vwl, gx);

    // 2) xxx = tanh(x_in @ time_maa_w1)
    gemm_k<64,32,32,4,4,false,1><<<dim3(4, MT_/64),128>>>(x_in, maa_w1, gxxx,
        MT_, 128, C_, C_, 128, 128, nullptr);

    // 3) mix_f = xxx[:, f*32:(f+1)*32] @ time_maa_w2[f]
    for (int f = 0; f < 4; f++)
        gemm_k<128,128,16,8,8,false,0><<<gBig,256>>>(gxxx + f*32,
            maa_w2 + (size_t)f*32*C_, gmixf[f],
            MT_, C_, 32, 128, C_, C_, nullptr);

    // 4) h32 = tanh(x @ time_maa_w_w1)
    gemm_k<64,32,32,4,4,false,1><<<dim3(1, MT_/64),128>>>(gx, w_w1, gh32,
        MT_, 32, C_, C_, 32, 32, nullptr);

    // 5) mw = h32 @ time_maa_w_w2
    gemm_k<128,128,16,8,8,false,0><<<gBig,256>>>(gh32, w_w2, gmw,
        MT_, C_, 32, 32, C_, C_, nullptr);

    // 6) xw = x + dxprev*(time_maa_w + mw)
    xw_kernel<<<ewBlocks,256>>>(gx, gmw, shift, maa_w, gxw);

    // 7) h128 = tanh(xw @ time_decay_w1)
    gemm_k<64,32,32,4,4,false,1><<<dim3(4, MT_/64),128>>>(gxw, dec_w1, gh128,
        MT_, 128, C_, C_, 128, 128, nullptr);

    // 8) w = time_decay + h128 @ time_decay_w2
    gemm_k<128,128,16,8,8,false,2><<<gBig,256>>>(gh128, dec_w2, gw,
        MT_, C_, 128, 128, C_, C_, t_decay);

    // 9) r,k,v,v2,decay
    rkv_kernel<<<ewBlocks,256>>>(gx, shift, gmix0, gmix1, gmix2, gmix3, gw,
        maa_r, maa_k, maa_v, maa_v2, t_rec, t_key,
        gr, gk, gv, gv2, gdec);

    // 10) WKV6 scan
    wkv_kernel<<<B_*H_,256>>>(gr, gk, gv, gdec, wkv_s, gy);

    // 11) LayerNorm(y + v2) -> yn hi/lo bf16
    ln_kernel<<<MT_,256>>>(gy, gv2, gamma, beta, yh, yl);

    // 12) out = ynorm @ output_w^T  (mma.sync, split-bf16)
    gemm_mma<<<gBig, 256, GM_SMEM>>>(yh, yl, owh, owl, outp);

    (void)in_sizes; (void)n_in; (void)out_size;
}

// round 6
// speedup vs baseline: 1.8710x; 1.2331x over previous
#include <cuda_runtime.h>
#include <cuda_bf16.h>
#include <cstdint>

// ---------------------------------------------------------------------------
// RWKV Tmix x060 block.  B=4, T=2048, C=2048, H=32, HS=64.
// Round 6 (= round 5 resubmit after broker timeout): ALL GEMMs on mma.sync
// bf16.  Big C x C GEMMs: split hi/lo 3-term.  Skinny (K=2048 -> N=128,
// tanh) and fat-N (K<=128 -> N=2048) GEMMs: single-term bf16.
// ---------------------------------------------------------------------------

#define B_  4
#define T_  2048
#define C_  2048
#define H_  32
#define MT_ (B_*T_)                       // 8192 rows
#define MTC_ ((size_t)MT_*(size_t)C_)     // 16777216 elements

__device__ __align__(128) float g_scratch[15ull*16777216ull + 4ull*1048576ull];

#define OFF_X    (0ull*16777216ull)
#define OFF_MIX0 (1ull*16777216ull)
#define OFF_MIX1 (2ull*16777216ull)
#define OFF_MIX2 (3ull*16777216ull)
#define OFF_MIX3 (4ull*16777216ull)
#define OFF_MW   (5ull*16777216ull)
#define OFF_W    (7ull*16777216ull)
#define OFF_R    (8ull*16777216ull)
#define OFF_K    (9ull*16777216ull)
#define OFF_V    (10ull*16777216ull)
#define OFF_V2   (11ull*16777216ull)
#define OFF_DEC  (12ull*16777216ull)
#define OFF_Y    (13ull*16777216ull)

// bf16 buffers
#define MEG 1048576ull
__device__ __align__(128) __nv_bfloat16 g_bf16[120ull*MEG];
#define BF_XH   (0ull*MEG)
#define BF_XL   (16ull*MEG)
#define BF_YH   (32ull*MEG)
#define BF_YL   (48ull*MEG)
#define BF_VWH  (64ull*MEG)
#define BF_VWL  (68ull*MEG)
#define BF_OWH  (72ull*MEG)
#define BF_OWL  (76ull*MEG)
#define BF_GXBF (80ull*MEG)      // x in bf16 (epilogue of GEMM 1)
#define BF_XWBF (96ull*MEG)      // xw in bf16
#define BF_XXX  (112ull*MEG)     // xxx [8192,128]
#define BF_H32  (114ull*MEG)     // h32 padded [8192,128]
#define BF_H128 (116ull*MEG)     // h128 [8192,128]
#define BF_W1T  (118ull*MEG)                 // [128,2048]
#define BF_WW1T (118ull*MEG +  262144ull)    // [128,2048] (rows>=32 zero)
#define BF_DW1T (118ull*MEG +  524288ull)    // [128,2048]
#define BF_W2T  (118ull*MEG +  786432ull)    // [4][2048,32]
#define BF_WW2T (118ull*MEG + 1048576ull)    // [2048,32]
#define BF_DW2T (118ull*MEG + 1114112ull)    // [2048,128]

// ======================== mma.sync helpers =================================
__device__ __forceinline__ uint32_t smem_u32(const void* p) {
    uint32_t a;
    asm("{ .reg .u64 t; cvta.to.shared.u64 t, %1; cvt.u32.u64 %0, t; }" : "=r"(a) : "l"(p));
    return a;
}

__device__ __forceinline__ void mma16816(float* d, const uint32_t* a, const uint32_t* b) {
    asm volatile(
        "mma.sync.aligned.m16n8k16.row.col.f32.bf16.bf16.f32 "
        "{%0,%1,%2,%3}, {%4,%5,%6,%7}, {%8,%9}, {%0,%1,%2,%3};"
        : "+f"(d[0]), "+f"(d[1]), "+f"(d[2]), "+f"(d[3])
        : "r"(a[0]), "r"(a[1]), "r"(a[2]), "r"(a[3]), "r"(b[0]), "r"(b[1]));
}

__device__ __forceinline__ void ldsm4(uint32_t* r, uint32_t addr) {
    asm volatile("ldmatrix.sync.aligned.m8n8.x4.shared.b16 {%0,%1,%2,%3}, [%4];"
        : "=r"(r[0]), "=r"(r[1]), "=r"(r[2]), "=r"(r[3]) : "r"(addr));
}

__device__ __forceinline__ void cp16(uint32_t dst, const void* src) {
    asm volatile("cp.async.cg.shared.global [%0], [%1], 16;" :: "r"(dst), "l"(src));
}
#define CP_COMMIT() asm volatile("cp.async.commit_group;" ::: "memory")
#define CP_WAIT(n)  asm volatile("cp.async.wait_group %0;" :: "n"(n) : "memory")

// ---------------------------------------------------------------------------
// Split-bf16 mma.sync GEMM:  C[8192,2048] = A @ B^T   (hi/lo 3-term)
// Block tile 128x128, BK=32, 8 warps (warp 64x32), cp.async double buffer.
// Optional bf16 copy of the output (Cbf).
// ---------------------------------------------------------------------------
#define GM_TILE_B  10240u        // 128 * 80 bytes
#define GM_BUF_B   40960u        // 4 tiles
#define GM_SMEM    81920         // 2 buffers

__global__ void __launch_bounds__(256, 2) gemm_mma(
    const __nv_bfloat16* __restrict__ a_hi, const __nv_bfloat16* __restrict__ a_lo,
    const __nv_bfloat16* __restrict__ b_hi, const __nv_bfloat16* __restrict__ b_lo,
    float* __restrict__ Cm, __nv_bfloat16* __restrict__ Cbf)
{
    extern __shared__ char smem[];
    const uint32_t sbase = smem_u32(smem);

    const int tid    = threadIdx.x;
    const int lane   = tid & 31;
    const int wid    = tid >> 5;
    const int warp_m = wid & 1;
    const int warp_n = wid >> 1;
    const int row0   = blockIdx.y * 128;
    const int col0   = blockIdx.x * 128;

    const __nv_bfloat16* sA0 = a_hi + (size_t)row0 * 2048;
    const __nv_bfloat16* sA1 = a_lo + (size_t)row0 * 2048;
    const __nv_bfloat16* sB0 = b_hi + (size_t)col0 * 2048;
    const __nv_bfloat16* sB1 = b_lo + (size_t)col0 * 2048;

    const int rr0 = tid >> 2;
    const int rr1 = rr0 + 64;
    const int cc  = (tid & 3) * 8;

    auto issue = [&](int ch, int buf) {
        const uint32_t bb = sbase + (uint32_t)buf * GM_BUF_B;
        const int kel = ch * 32;
#define ONE_TILE(SRC, TOFF)                                                    \
        cp16(bb + (TOFF) + (uint32_t)rr0*80u + (uint32_t)(tid&3)*16u,          \
             (SRC) + (size_t)rr0*2048 + kel + cc);                             \
        cp16(bb + (TOFF) + (uint32_t)rr1*80u + (uint32_t)(tid&3)*16u,          \
             (SRC) + (size_t)rr1*2048 + kel + cc);
        ONE_TILE(sA0, 0u)
        ONE_TILE(sA1, GM_TILE_B)
        ONE_TILE(sB0, 2u*GM_TILE_B)
        ONE_TILE(sB1, 3u*GM_TILE_B)
#undef ONE_TILE
        CP_COMMIT();
    };

    float acc[4][4][4];
#pragma unroll
    for (int i = 0; i < 4; i++)
#pragma unroll
        for (int j = 0; j < 4; j++)
#pragma unroll
            for (int q = 0; q < 4; q++) acc[i][j][q] = 0.f;

    issue(0, 0);

    const uint32_t lrow  = (uint32_t)(lane & 15);
    const uint32_t khalf = (uint32_t)((lane >> 4) << 3);

    for (int ch = 0; ch < 64; ch++) {
        if (ch < 63) { issue(ch + 1, (ch + 1) & 1); CP_WAIT(1); }
        else         { CP_WAIT(0); }
        __syncthreads();

        const uint32_t bb = sbase + (uint32_t)(ch & 1) * GM_BUF_B;
        const uint32_t aH = bb;
        const uint32_t aL = bb + GM_TILE_B;
        const uint32_t bH = bb + 2u*GM_TILE_B;
        const uint32_t bL = bb + 3u*GM_TILE_B;

#pragma unroll
        for (int k16 = 0; k16 < 32; k16 += 16) {
            const uint32_t kb = ((uint32_t)k16 + khalf) * 2u;
            uint32_t af[4][4], bf[4][2], bl[4][2];

#pragma unroll
            for (int f = 0; f < 4; f++)
                ldsm4(af[f], aH + (uint32_t)(warp_m*64 + f*16 + lrow)*80u + kb);
#pragma unroll
            for (int pr = 0; pr < 2; pr++) {
                uint32_t r[4];
                ldsm4(r, bH + (uint32_t)(warp_n*32 + pr*16 + lrow)*80u + kb);
                bf[2*pr+0][0] = r[0]; bf[2*pr+0][1] = r[2];
                bf[2*pr+1][0] = r[1]; bf[2*pr+1][1] = r[3];
            }
#pragma unroll
            for (int pr = 0; pr < 2; pr++) {
                uint32_t r[4];
                ldsm4(r, bL + (uint32_t)(warp_n*32 + pr*16 + lrow)*80u + kb);
                bl[2*pr+0][0] = r[0]; bl[2*pr+0][1] = r[2];
                bl[2*pr+1][0] = r[1]; bl[2*pr+1][1] = r[3];
            }
#pragma unroll
            for (int mf = 0; mf < 4; mf++)
#pragma unroll
                for (int nf = 0; nf < 4; nf++) {
                    mma16816(acc[mf][nf], af[mf], bf[nf]);
                    mma16816(acc[mf][nf], af[mf], bl[nf]);
                }
#pragma unroll
            for (int f = 0; f < 4; f++)
                ldsm4(af[f], aL + (uint32_t)(warp_m*64 + f*16 + lrow)*80u + kb);
#pragma unroll
            for (int mf = 0; mf < 4; mf++)
#pragma unroll
                for (int nf = 0; nf < 4; nf++)
                    mma16816(acc[mf][nf], af[mf], bf[nf]);
        }
        __syncthreads();
    }

    const int erow = row0 + warp_m*64 + (lane >> 2);
    const int ecol = col0 + warp_n*32 + (lane & 3)*2;
#pragma unroll
    for (int mf = 0; mf < 4; mf++) {
#pragma unroll
        for (int nf = 0; nf < 4; nf++) {
            float* p0 = Cm + (size_t)(erow + mf*16    )*2048 + ecol + nf*8;
            float* p1 = Cm + (size_t)(erow + mf*16 + 8)*2048 + ecol + nf*8;
            *(float2*)p0 = make_float2(acc[mf][nf][0], acc[mf][nf][1]);
            *(float2*)p1 = make_float2(acc[mf][nf][2], acc[mf][nf][3]);
            if (Cbf) {
                __nv_bfloat162* q0 = (__nv_bfloat162*)(Cbf + (size_t)(erow + mf*16    )*2048 + ecol + nf*8);
                __nv_bfloat162* q1 = (__nv_bfloat162*)(Cbf + (size_t)(erow + mf*16 + 8)*2048 + ecol + nf*8);
                *q0 = __floats2bfloat162_rn(acc[mf][nf][0], acc[mf][nf][1]);
                *q1 = __floats2bfloat162_rn(acc[mf][nf][2], acc[mf][nf][3]);
            }
        }
    }
}

// ---------------------------------------------------------------------------
// Skinny GEMM:  C[8192,128] (bf16) = tanh( A[8192,2048] @ Bt[128,2048]^T )
// Block tile 64x128, BK=32, 8 warps (warp 32x32), double buffered.
// ---------------------------------------------------------------------------
#define GS_A_B   5120u           // 64 * 80
#define GS_BUF_B 15360u          // A tile + B tile (128*80)

__global__ void __launch_bounds__(256) gemm_skinny(
    const __nv_bfloat16* __restrict__ A,     // lda = 2048
    const __nv_bfloat16* __restrict__ Bt,    // [128,2048]
    __nv_bfloat16* __restrict__ C)           // ldc = 128
{
    __shared__ char smem[2*15360];
    const uint32_t sbase = smem_u32(smem);

    const int tid    = threadIdx.x;
    const int lane   = tid & 31;
    const int wid    = tid >> 5;
    const int warp_m = wid & 1;
    const int warp_n = wid >> 1;
    const int row0   = blockIdx.x * 64;

    const __nv_bfloat16* Ab = A + (size_t)row0 * 2048;

    auto issue = [&](int ch, int buf) {
        const uint32_t bb = sbase + (uint32_t)buf * GS_BUF_B;
        const int kel = ch * 32;
        cp16(bb + (uint32_t)(tid>>2)*80u + (uint32_t)(tid&3)*16u,
             Ab + (size_t)(tid>>2)*2048 + kel + (tid&3)*8);
#pragma unroll
        for (int s = 0; s < 2; s++) {
            int idx = tid + s*256;
            cp16(bb + GS_A_B + (uint32_t)(idx>>2)*80u + (uint32_t)(idx&3)*16u,
                 Bt + (size_t)(idx>>2)*2048 + kel + (idx&3)*8);
        }
        CP_COMMIT();
    };

    float acc[2][4][4];
#pragma unroll
    for (int i = 0; i < 2; i++)
#pragma unroll
        for (int j = 0; j < 4; j++)
#pragma unroll
            for (int q = 0; q < 4; q++) acc[i][j][q] = 0.f;

    issue(0, 0);

    const uint32_t lrow  = (uint32_t)(lane & 15);
    const uint32_t khalf = (uint32_t)((lane >> 4) << 3);

    for (int ch = 0; ch < 64; ch++) {
        if (ch < 63) { issue(ch + 1, (ch + 1) & 1); CP_WAIT(1); }
        else         { CP_WAIT(0); }
        __syncthreads();

        const uint32_t aB = sbase + (uint32_t)(ch & 1) * GS_BUF_B;
        const uint32_t bB = aB + GS_A_B;

#pragma unroll
        for (int k16 = 0; k16 < 32; k16 += 16) {
            const uint32_t kb = ((uint32_t)k16 + khalf) * 2u;
            uint32_t af[2][4], bfr[4][2];
#pragma unroll
            for (int f = 0; f < 2; f++)
                ldsm4(af[f], aB + (uint32_t)(warp_m*32 + f*16 + lrow)*80u + kb);
#pragma unroll
            for (int pr = 0; pr < 2; pr++) {
                uint32_t r[4];
                ldsm4(r, bB + (uint32_t)(warp_n*32 + pr*16 + lrow)*80u + kb);
                bfr[2*pr+0][0] = r[0]; bfr[2*pr+0][1] = r[2];
                bfr[2*pr+1][0] = r[1]; bfr[2*pr+1][1] = r[3];
            }
#pragma unroll
            for (int mf = 0; mf < 2; mf++)
#pragma unroll
                for (int nf = 0; nf < 4; nf++)
                    mma16816(acc[mf][nf], af[mf], bfr[nf]);
        }
        __syncthreads();
    }

    const int erow = row0 + warp_m*32 + (lane >> 2);
    const int ecol = warp_n*32 + (lane & 3)*2;
#pragma unroll
    for (int mf = 0; mf < 2; mf++) {
#pragma unroll
        for (int nf = 0; nf < 4; nf++) {
            __nv_bfloat162* q0 = (__nv_bfloat162*)(C + (size_t)(erow + mf*16    )*128 + ecol + nf*8);
            __nv_bfloat162* q1 = (__nv_bfloat162*)(C + (size_t)(erow + mf*16 + 8)*128 + ecol + nf*8);
            *q0 = __floats2bfloat162_rn(tanhf(acc[mf][nf][0]), tanhf(acc[mf][nf][1]));
            *q1 = __floats2bfloat162_rn(tanhf(acc[mf][nf][2]), tanhf(acc[mf][nf][3]));
        }
    }
}

// ---------------------------------------------------------------------------
// Fat-N GEMM:  C[8192,2048] (fp32, +bias) = A[8192,K] @ Bt[2048,K]^T, K=nk32*32
// Block tile 128x128, whole K loaded once.  8 warps (warp 64x32).
// ---------------------------------------------------------------------------
__global__ void __launch_bounds__(256) gemm_fatN(
    const __nv_bfloat16* __restrict__ A, int lda,
    const __nv_bfloat16* __restrict__ Bt,
    float* __restrict__ Cm, const float* __restrict__ bias, int nk32)
{
    extern __shared__ char smem2[];
    const uint32_t sbase = smem_u32(smem2);

    const int tid    = threadIdx.x;
    const int lane   = tid & 31;
    const int wid    = tid >> 5;
    const int warp_m = wid & 1;
    const int warp_n = wid >> 1;
    const int row0   = blockIdx.y * 128;
    const int col0   = blockIdx.x * 128;
    const int ldb    = nk32 * 32;

    for (int ch = 0; ch < nk32; ch++) {
        const uint32_t bb = sbase + (uint32_t)ch * 20480u;
#pragma unroll
        for (int s = 0; s < 2; s++) {
            int idx = tid + s*256;
            int row = idx >> 2, quad = idx & 3;
            cp16(bb + (uint32_t)row*80u + (uint32_t)quad*16u,
                 A + (size_t)(row0 + row)*lda + ch*32 + quad*8);
            cp16(bb + 10240u + (uint32_t)row*80u + (uint32_t)quad*16u,
                 Bt + (size_t)(col0 + row)*ldb + ch*32 + quad*8);
        }
    }
    CP_COMMIT();
    CP_WAIT(0);
    __syncthreads();

    float acc[4][4][4];
#pragma unroll
    for (int i = 0; i < 4; i++)
#pragma unroll
        for (int j = 0; j < 4; j++)
#pragma unroll
            for (int q = 0; q < 4; q++) acc[i][j][q] = 0.f;

    const uint32_t lrow  = (uint32_t)(lane & 15);
    const uint32_t khalf = (uint32_t)((lane >> 4) << 3);

    for (int ch = 0; ch < nk32; ch++) {
        const uint32_t aB = sbase + (uint32_t)ch * 20480u;
        const uint32_t bB = aB + 10240u;
#pragma unroll
        for (int k16 = 0; k16 < 32; k16 += 16) {
            const uint32_t kb = ((uint32_t)k16 + khalf) * 2u;
            uint32_t af[4][4], bfr[4][2];
#pragma unroll
            for (int f = 0; f < 4; f++)
                ldsm4(af[f], aB + (uint32_t)(warp_m*64 + f*16 + lrow)*80u + kb);
#pragma unroll
            for (int pr = 0; pr < 2; pr++) {
                uint32_t r[4];
                ldsm4(r, bB + (uint32_t)(warp_n*32 + pr*16 + lrow)*80u + kb);
                bfr[2*pr+0][0] = r[0]; bfr[2*pr+0][1] = r[2];
                bfr[2*pr+1][0] = r[1]; bfr[2*pr+1][1] = r[3];
            }
#pragma unroll
            for (int mf = 0; mf < 4; mf++)
#pragma unroll
                for (int nf = 0; nf < 4; nf++)
                    mma16816(acc[mf][nf], af[mf], bfr[nf]);
        }
    }

    const int erow = row0 + warp_m*64 + (lane >> 2);
    const int ecol = col0 + warp_n*32 + (lane & 3)*2;
#pragma unroll
    for (int mf = 0; mf < 4; mf++) {
#pragma unroll
        for (int nf = 0; nf < 4; nf++) {
            float b0 = 0.f, b1 = 0.f;
            if (bias) { b0 = bias[ecol + nf*8]; b1 = bias[ecol + nf*8 + 1]; }
            float* p0 = Cm + (size_t)(erow + mf*16    )*2048 + ecol + nf*8;
            float* p1 = Cm + (size_t)(erow + mf*16 + 8)*2048 + ecol + nf*8;
            *(float2*)p0 = make_float2(acc[mf][nf][0] + b0, acc[mf][nf][1] + b1);
            *(float2*)p1 = make_float2(acc[mf][nf][2] + b0, acc[mf][nf][3] + b1);
        }
    }
}

// ---------------------------------------------------------------------------
// fp32 -> (hi, lo) bf16 conversion, vectorized by 4.
// ---------------------------------------------------------------------------
__global__ void cvt_hilo(const float* __restrict__ in,
                         __nv_bfloat16* __restrict__ hi,
                         __nv_bfloat16* __restrict__ lo, int n4)
{
    int i = blockIdx.x * blockDim.x + threadIdx.x;
    if (i >= n4) return;
    float4 f = ((const float4*)in)[i];
    __nv_bfloat16 h0 = __float2bfloat16(f.x), h1 = __float2bfloat16(f.y);
    __nv_bfloat16 h2 = __float2bfloat16(f.z), h3 = __float2bfloat16(f.w);
    __nv_bfloat16 l0 = __float2bfloat16(f.x - __bfloat162float(h0));
    __nv_bfloat16 l1 = __float2bfloat16(f.y - __bfloat162float(h1));
    __nv_bfloat16 l2 = __float2bfloat16(f.z - __bfloat162float(h2));
    __nv_bfloat16 l3 = __float2bfloat16(f.w - __bfloat162float(h3));
    uint2 up, lp;
    ((__nv_bfloat16*)&up)[0] = h0; ((__nv_bfloat16*)&up)[1] = h1;
    ((__nv_bfloat16*)&up)[2] = h2; ((__nv_bfloat16*)&up)[3] = h3;
    ((__nv_bfloat16*)&lp)[0] = l0; ((__nv_bfloat16*)&lp)[1] = l1;
    ((__nv_bfloat16*)&lp)[2] = l2; ((__nv_bfloat16*)&lp)[3] = l3;
    ((uint2*)hi)[i] = up;
    ((uint2*)lo)[i] = lp;
}

// Transpose weight fp32[K,N] -> bf16[NPAD,K], rows >= N zero-filled.
__global__ void cvt_wt(const float* __restrict__ in, __nv_bfloat16* __restrict__ out,
                       int K, int N, int NPAD)
{
    int idx = blockIdx.x * blockDim.x + threadIdx.x;
    if (idx >= NPAD * K) return;
    int n = idx / K, k = idx - n * K;
    float v = (n < N) ? in[(size_t)k * N + n] : 0.f;
    out[idx] = __float2bfloat16(v);
}

// ======================== elementwise / scan / LN ==========================
__global__ void xw_kernel(const float* __restrict__ x, const float* __restrict__ mw,
                          const float* __restrict__ shift, const float* __restrict__ maa_w,
                          __nv_bfloat16* __restrict__ xw)
{
    size_t idx = (size_t)blockIdx.x * blockDim.x + threadIdx.x;
    int   c  = (int)(idx & (C_-1));
    size_t bt = idx >> 11;
    int   t  = (int)(bt & (T_-1));
    int   b  = (int)(bt >> 11);
    float xv   = x[idx];
    float prev = t ? x[idx - C_] : shift[b*C_ + c];
    xw[idx] = __float2bfloat16(xv + (prev - xv) * (maa_w[c] + mw[idx]));
}

__global__ void rkv_kernel(const float* __restrict__ x,  const float* __restrict__ shift,
                           const float* __restrict__ mr, const float* __restrict__ mk,
                           const float* __restrict__ mv, const float* __restrict__ mv2,
                           const float* __restrict__ w,
                           const float* __restrict__ maa_r, const float* __restrict__ maa_k,
                           const float* __restrict__ maa_v, const float* __restrict__ maa_v2,
                           const float* __restrict__ t_r,   const float* __restrict__ t_k,
                           float* __restrict__ r, float* __restrict__ k,
                           float* __restrict__ v, float* __restrict__ v2,
                           float* __restrict__ dec)
{
    size_t idx = (size_t)blockIdx.x * blockDim.x + threadIdx.x;
    int   c  = (int)(idx & (C_-1));
    size_t bt = idx >> 11;
    int   t  = (int)(bt & (T_-1));
    int   b  = (int)(bt >> 11);
    float xv   = x[idx];
    float prev = t ? x[idx - C_] : shift[b*C_ + c];
    float dx   = prev - xv;
    float d    = expf(-expf(w[idx]));
    r[idx]   = (xv + dx*(maa_r[c]  + mr[idx]))  * t_r[c];
    k[idx]   = (xv + dx*(maa_k[c]  + mk[idx]))  * t_k[c] * (1.f - d);
    v[idx]   =  xv + dx*(maa_v[c]  + mv[idx]);
    v2[idx]  =  xv + dx*(maa_v2[c] + mv2[idx]);
    dec[idx] = d;
}

__global__ void __launch_bounds__(256) wkv_kernel(
    const float* __restrict__ r, const float* __restrict__ k,
    const float* __restrict__ v, const float* __restrict__ d,
    const float* __restrict__ s0, float* __restrict__ y)
{
    const int bh = blockIdx.x;
    const int b  = bh >> 5;
    const int h  = bh & 31;
    const int tid = threadIdx.x;
    const int q  = tid & 3;
    const int j  = tid >> 2;

    __shared__ float sbuf[2][4][64];

    float S[16];
    const size_t sbase = (size_t)bh * 64 * 64;
#pragma unroll
    for (int ii = 0; ii < 16; ii++)
        S[ii] = s0[sbase + (size_t)(q*16 + ii)*64 + j];

    const int arr = tid >> 6;
    const int li  = tid & 63;
    const float* src = (arr == 0) ? r : (arr == 1) ? k : (arr == 2) ? v : d;

    size_t base = (size_t)b * T_ * C_ + (size_t)h * 64;
    int p = 0;
    for (int t = 0; t < T_; t++) {
        sbuf[p][arr][li] = src[base + li];
        __syncthreads();

        const float  vv = sbuf[p][2][j];
        const float* rs = &sbuf[p][0][q*16];
        const float* ks = &sbuf[p][1][q*16];
        const float* ds = &sbuf[p][3][q*16];

        float y0 = 0.f, y1 = 0.f, y2 = 0.f, y3 = 0.f;
#pragma unroll
        for (int ii = 0; ii < 16; ii += 4) {
            float s0r = S[ii+0], s1r = S[ii+1], s2r = S[ii+2], s3r = S[ii+3];
            y0 = fmaf(rs[ii+0], s0r, y0);
            y1 = fmaf(rs[ii+1], s1r, y1);
            y2 = fmaf(rs[ii+2], s2r, y2);
            y3 = fmaf(rs[ii+3], s3r, y3);
            S[ii+0] = fmaf(ds[ii+0], s0r, ks[ii+0]*vv);
            S[ii+1] = fmaf(ds[ii+1], s1r, ks[ii+1]*vv);
            S[ii+2] = fmaf(ds[ii+2], s2r, ks[ii+2]*vv);
            S[ii+3] = fmaf(ds[ii+3], s3r, ks[ii+3]*vv);
        }
        float yp = (y0 + y1) + (y2 + y3);
        yp += __shfl_xor_sync(0xffffffffu, yp, 1);
        yp += __shfl_xor_sync(0xffffffffu, yp, 2);
        if (q == 0) y[base + j] = yp;

        base += C_;
        p ^= 1;
    }
}

__global__ void __launch_bounds__(256) ln_kernel(
    const float* __restrict__ y, const float* __restrict__ v2,
    const float* __restrict__ gamma, const float* __restrict__ beta,
    __nv_bfloat16* __restrict__ yh, __nv_bfloat16* __restrict__ yl)
{
    const int row = blockIdx.x;
    const int tid = threadIdx.x;
    __shared__ float buf[C_];
    __shared__ float aux[2][8];

    const size_t base = (size_t)row * C_;
    float s = 0.f, s2 = 0.f;
    for (int c = tid; c < C_; c += 256) {
        float val = y[base + c] + v2[base + c];
        buf[c] = val;
        s += val; s2 += val*val;
    }
#pragma unroll
    for (int o = 16; o; o >>= 1) {
        s  += __shfl_xor_sync(0xffffffffu, s,  o);
        s2 += __shfl_xor_sync(0xffffffffu, s2, o);
    }
    if ((tid & 31) == 0) { aux[0][tid >> 5] = s; aux[1][tid >> 5] = s2; }
    __syncthreads();
    float ts = 0.f, ts2 = 0.f;
#pragma unroll
    for (int wpi = 0; wpi < 8; wpi++) { ts += aux[0][wpi]; ts2 += aux[1][wpi]; }
    const float mu  = ts * (1.f / C_);
    const float var = ts2 * (1.f / C_) - mu*mu;
    const float inv = rsqrtf(var + 1e-5f);
    for (int c = tid; c < C_; c += 256) {
        float o = (buf[c] - mu) * inv * gamma[c] + beta[c];
        __nv_bfloat16 h = __float2bfloat16(o);
        yh[base + c] = h;
        yl[base + c] = __float2bfloat16(o - __bfloat162float(h));
    }
}

// ---------------------------------------------------------------------------
extern "C" void kernel_launch(void* const* d_in, const int* in_sizes, int n_in,
                              void* d_out, int out_size)
{
    const float* x_in    = (const float*)d_in[0];
    const float* shift   = (const float*)d_in[1];
    const float* wkv_s   = (const float*)d_in[2];
    const float* maa_r   = (const float*)d_in[3];
    const float* maa_k   = (const float*)d_in[4];
    const float* maa_v   = (const float*)d_in[5];
    const float* maa_v2  = (const float*)d_in[6];
    const float* maa_w1  = (const float*)d_in[7];
    const float* maa_w2  = (const float*)d_in[8];
    const float* maa_w   = (const float*)d_in[9];
    const float* w_w1    = (const float*)d_in[10];
    const float* w_w2    = (const float*)d_in[11];
    const float* t_decay = (const float*)d_in[12];
    const float* dec_w1  = (const float*)d_in[13];
    const float* dec_w2  = (const float*)d_in[14];
    /* d_in[15] time_faaaa: dead (u = 0 in reference) */
    const float* t_rec   = (const float*)d_in[16];
    const float* t_key   = (const float*)d_in[17];
    const float* val_w   = (const float*)d_in[18];
    const float* out_w   = (const float*)d_in[19];
    const float* gamma   = (const float*)d_in[20];
    const float* beta    = (const float*)d_in[21];
    float* outp = (float*)d_out;

    float* sp = nullptr;
    cudaGetSymbolAddress((void**)&sp, g_scratch);
    __nv_bfloat16* bp = nullptr;
    cudaGetSymbolAddress((void**)&bp, g_bf16);

    float* gx    = sp + OFF_X;
    float* gmixf[4] = {sp + OFF_MIX0, sp + OFF_MIX1, sp + OFF_MIX2, sp + OFF_MIX3};
    float* gmw   = sp + OFF_MW;
    float* gw    = sp + OFF_W;
    float* gr    = sp + OFF_R;
    float* gk    = sp + OFF_K;
    float* gv    = sp + OFF_V;
    float* gv2   = sp + OFF_V2;
    float* gdec  = sp + OFF_DEC;
    float* gy    = sp + OFF_Y;

    __nv_bfloat16* xh   = bp + BF_XH;
    __nv_bfloat16* xl   = bp + BF_XL;
    __nv_bfloat16* yh   = bp + BF_YH;
    __nv_bfloat16* yl   = bp + BF_YL;
    __nv_bfloat16* vwh  = bp + BF_VWH;
    __nv_bfloat16* vwl  = bp + BF_VWL;
    __nv_bfloat16* owh  = bp + BF_OWH;
    __nv_bfloat16* owl  = bp + BF_OWL;
    __nv_bfloat16* gxbf = bp + BF_GXBF;
    __nv_bfloat16* xwbf = bp + BF_XWBF;
    __nv_bfloat16* xxxb = bp + BF_XXX;
    __nv_bfloat16* h32p = bp + BF_H32;
    __nv_bfloat16* h128 = bp + BF_H128;
    __nv_bfloat16* w1t  = bp + BF_W1T;
    __nv_bfloat16* ww1t = bp + BF_WW1T;
    __nv_bfloat16* dw1t = bp + BF_DW1T;
    __nv_bfloat16* w2t  = bp + BF_W2T;
    __nv_bfloat16* ww2t = bp + BF_WW2T;
    __nv_bfloat16* dw2t = bp + BF_DW2T;

    cudaFuncSetAttribute(gemm_mma,  cudaFuncAttributeMaxDynamicSharedMemorySize, GM_SMEM);
    cudaFuncSetAttribute(gemm_fatN, cudaFuncAttributeMaxDynamicSharedMemorySize, 81920);

    const dim3 gBig(C_/128, MT_/128);          // (16, 64)
    const unsigned ewBlocks = (unsigned)(MTC_ / 256);

    // 0) conversions
    cvt_hilo<<<(unsigned)(MTC_/4/256), 256>>>(x_in,  xh,  xl,  (int)(MTC_/4));
    cvt_hilo<<<(unsigned)(C_*(size_t)C_/4/256), 256>>>(val_w, vwh, vwl, C_*C_/4);
    cvt_hilo<<<(unsigned)(C_*(size_t)C_/4/256), 256>>>(out_w, owh, owl, C_*C_/4);
    cvt_wt<<<1024, 256>>>(maa_w1, w1t,  2048, 128, 128);
    cvt_wt<<<1024, 256>>>(w_w1,   ww1t, 2048,  32, 128);
    cvt_wt<<<1024, 256>>>(dec_w1, dw1t, 2048, 128, 128);
    for (int f = 0; f < 4; f++)
        cvt_wt<<<256, 256>>>(maa_w2 + (size_t)f*32*2048, w2t + (size_t)f*65536, 32, 2048, 2048);
    cvt_wt<<<256, 256>>>(w_w2,   ww2t,  32, 2048, 2048);
    cvt_wt<<<1024, 256>>>(dec_w2, dw2t, 128, 2048, 2048);

    // 1) x = x_in @ value_w^T  (split-bf16)  -> gx fp32 + gxbf bf16
    gemm_mma<<<gBig, 256, GM_SMEM>>>(xh, xl, vwh, vwl, gx, gxbf);

    // 2) xxx = tanh(x_in @ maa_w1)  -> bf16 [8192,128]
    gemm_skinny<<<MT_/64, 256>>>(xh, w1t, xxxb);

    // 3) mix_f = xxx[:, f*32:] @ maa_w2[f]
    for (int f = 0; f < 4; f++)
        gemm_fatN<<<gBig, 256, 20480>>>(xxxb + f*32, 128, w2t + (size_t)f*65536,
                                        gmixf[f], nullptr, 1);

    // 4) h32 = tanh(x @ w_w1)  (padded to N=128)
    gemm_skinny<<<MT_/64, 256>>>(gxbf, ww1t, h32p);

    // 5) mw = h32 @ w_w2
    gemm_fatN<<<gBig, 256, 20480>>>(h32p, 128, ww2t, gmw, nullptr, 1);

    // 6) xw -> bf16
    xw_kernel<<<ewBlocks,256>>>(gx, gmw, shift, maa_w, xwbf);

    // 7) h128 = tanh(xw @ dec_w1)
    gemm_skinny<<<MT_/64, 256>>>(xwbf, dw1t, h128);

    // 8) w = time_decay + h128 @ dec_w2
    gemm_fatN<<<gBig, 256, 81920>>>(h128, 128, dw2t, gw, t_decay, 4);

    // 9) r,k,v,v2,decay
    rkv_kernel<<<ewBlocks,256>>>(gx, shift, gmixf[0], gmixf[1], gmixf[2], gmixf[3], gw,
        maa_r, maa_k, maa_v, maa_v2, t_rec, t_key,
        gr, gk, gv, gv2, gdec);

    // 10) WKV6 scan
    wkv_kernel<<<B_*H_,256>>>(gr, gk, gv, gdec, wkv_s, gy);

    // 11) LayerNorm(y + v2) -> yh/yl
    ln_kernel<<<MT_,256>>>(gy, gv2, gamma, beta, yh, yl);

    // 12) out = ynorm @ output_w^T  (split-bf16)
    gemm_mma<<<gBig, 256, GM_SMEM>>>(yh, yl, owh, owl, outp, nullptr);

    (void)in_sizes; (void)n_in; (void)out_size;
}